// round 1
// baseline (speedup 1.0000x reference)
#include <cuda_runtime.h>
#include <math.h>

// Problem constants
#define LSEQ 2048
#define DMODEL 2048
#define NH 32
#define NKV 8
#define HD 64
#define NB 2
#define WWIN 1024
#define KVD (NKV*HD)   // 512
#define MROWS (NB*LSEQ) // 4096

// ---------------- scratch (device globals; no runtime allocation) ----------------
static __device__ float g_q[(long long)MROWS * DMODEL];     // [B*L][2048]
static __device__ float g_k[(long long)MROWS * KVD];        // [B*L][512]
static __device__ float g_v[(long long)MROWS * KVD];        // [B*L][512]
static __device__ float g_s[(long long)NB * NH * LSEQ * LSEQ]; // scores/probs, 1 GB
static __device__ float g_ao[(long long)MROWS * DMODEL];    // attn out [B*L][2048]

// dead 128x128 tile: every (i,j) in tile satisfies  i-W <= j < i
__host__ __device__ __forceinline__ bool tile_dead(int i0, int j0) {
    return (j0 + 127 < i0) && (j0 >= i0 + 127 - WWIN);
}

// ---------------- generic SGEMM: C[M,N] = A[M,K] @ B[K,N], 128x128x16, 8x8 micro ----
__global__ __launch_bounds__(256) void sgemm128(const float* __restrict__ A,
                                                const float* __restrict__ B,
                                                float* __restrict__ C,
                                                int M, int N, int K) {
    __shared__ float As[16][128];
    __shared__ float Bs[16][128];
    const int tid = threadIdx.x;
    const int m0 = blockIdx.y * 128, n0 = blockIdx.x * 128;
    const int tx = tid & 15, ty = tid >> 4;
    const int ar = tid >> 2, ac = (tid & 3) * 4;    // A loads (transpose-on-store)
    const int br = tid >> 5, bc = (tid & 31) * 4;   // B loads (direct)
    float acc[8][8] = {};
    for (int k0 = 0; k0 < K; k0 += 16) {
        #pragma unroll
        for (int r = 0; r < 2; r++) {
            int row = ar + r * 64;
            float4 av = *(const float4*)(A + (long long)(m0 + row) * K + k0 + ac);
            As[ac + 0][row] = av.x; As[ac + 1][row] = av.y;
            As[ac + 2][row] = av.z; As[ac + 3][row] = av.w;
        }
        #pragma unroll
        for (int r = 0; r < 2; r++) {
            int row = br + r * 8;
            *(float4*)(&Bs[row][bc]) = *(const float4*)(B + (long long)(k0 + row) * N + n0 + bc);
        }
        __syncthreads();
        #pragma unroll
        for (int kk = 0; kk < 16; kk++) {
            float a[8], b[8];
            *(float4*)(a)     = *(const float4*)(&As[kk][ty * 8]);
            *(float4*)(a + 4) = *(const float4*)(&As[kk][ty * 8 + 4]);
            *(float4*)(b)     = *(const float4*)(&Bs[kk][tx * 8]);
            *(float4*)(b + 4) = *(const float4*)(&Bs[kk][tx * 8 + 4]);
            #pragma unroll
            for (int i = 0; i < 8; i++)
                #pragma unroll
                for (int j = 0; j < 8; j++)
                    acc[i][j] += a[i] * b[j];
        }
        __syncthreads();
    }
    #pragma unroll
    for (int i = 0; i < 8; i++) {
        float* cp = C + (long long)(m0 + ty * 8 + i) * N + n0 + tx * 8;
        *(float4*)(cp)     = make_float4(acc[i][0], acc[i][1], acc[i][2], acc[i][3]);
        *(float4*)(cp + 4) = make_float4(acc[i][4], acc[i][5], acc[i][6], acc[i][7]);
    }
}

// K and V projections fused in one launch (blockIdx.z selects which)
__global__ __launch_bounds__(256) void sgemm128_kv(const float* __restrict__ A,
                                                   const float* __restrict__ Bk,
                                                   const float* __restrict__ Bv,
                                                   float* __restrict__ Ck,
                                                   float* __restrict__ Cv) {
    const int M = MROWS, N = KVD, K = DMODEL;
    const float* B = (blockIdx.z == 0) ? Bk : Bv;
    float* C = (blockIdx.z == 0) ? Ck : Cv;
    __shared__ float As[16][128];
    __shared__ float Bs[16][128];
    const int tid = threadIdx.x;
    const int m0 = blockIdx.y * 128, n0 = blockIdx.x * 128;
    const int tx = tid & 15, ty = tid >> 4;
    const int ar = tid >> 2, ac = (tid & 3) * 4;
    const int br = tid >> 5, bc = (tid & 31) * 4;
    float acc[8][8] = {};
    for (int k0 = 0; k0 < K; k0 += 16) {
        #pragma unroll
        for (int r = 0; r < 2; r++) {
            int row = ar + r * 64;
            float4 av = *(const float4*)(A + (long long)(m0 + row) * K + k0 + ac);
            As[ac + 0][row] = av.x; As[ac + 1][row] = av.y;
            As[ac + 2][row] = av.z; As[ac + 3][row] = av.w;
        }
        #pragma unroll
        for (int r = 0; r < 2; r++) {
            int row = br + r * 8;
            *(float4*)(&Bs[row][bc]) = *(const float4*)(B + (long long)(k0 + row) * N + n0 + bc);
        }
        __syncthreads();
        #pragma unroll
        for (int kk = 0; kk < 16; kk++) {
            float a[8], b[8];
            *(float4*)(a)     = *(const float4*)(&As[kk][ty * 8]);
            *(float4*)(a + 4) = *(const float4*)(&As[kk][ty * 8 + 4]);
            *(float4*)(b)     = *(const float4*)(&Bs[kk][tx * 8]);
            *(float4*)(b + 4) = *(const float4*)(&Bs[kk][tx * 8 + 4]);
            #pragma unroll
            for (int i = 0; i < 8; i++)
                #pragma unroll
                for (int j = 0; j < 8; j++)
                    acc[i][j] += a[i] * b[j];
        }
        __syncthreads();
    }
    #pragma unroll
    for (int i = 0; i < 8; i++) {
        float* cp = C + (long long)(m0 + ty * 8 + i) * N + n0 + tx * 8;
        *(float4*)(cp)     = make_float4(acc[i][0], acc[i][1], acc[i][2], acc[i][3]);
        *(float4*)(cp + 4) = make_float4(acc[i][4], acc[i][5], acc[i][6], acc[i][7]);
    }
}

// ---------------- scores: S[bh][i][j] = (Q_i . K_j)/8, mask -> -1e10; skip dead tiles ---
__global__ __launch_bounds__(256) void scores_kernel(const float* __restrict__ Q,
                                                     const float* __restrict__ Kb,
                                                     float* __restrict__ S) {
    const int bh = blockIdx.z;               // 0..63
    const int b = bh >> 5, h = bh & 31, kh = h >> 2;
    const int i0 = blockIdx.y * 128, j0 = blockIdx.x * 128;
    if (tile_dead(i0, j0)) return;
    __shared__ float Qs[16][128];
    __shared__ float Ks[16][128];
    const int tid = threadIdx.x, tx = tid & 15, ty = tid >> 4;
    const int r0 = tid >> 2, cg = (tid & 3) * 4;
    const float* qbase = Q + (long long)(b * LSEQ + i0) * DMODEL + h * HD;
    const float* kbase = Kb + (long long)(b * LSEQ + j0) * KVD + kh * HD;
    float acc[8][8] = {};
    for (int kc = 0; kc < HD; kc += 16) {
        #pragma unroll
        for (int r = 0; r < 2; r++) {
            int row = r0 + r * 64;
            float4 qv = *(const float4*)(qbase + (long long)row * DMODEL + kc + cg);
            Qs[cg + 0][row] = qv.x; Qs[cg + 1][row] = qv.y;
            Qs[cg + 2][row] = qv.z; Qs[cg + 3][row] = qv.w;
            float4 kv = *(const float4*)(kbase + (long long)row * KVD + kc + cg);
            Ks[cg + 0][row] = kv.x; Ks[cg + 1][row] = kv.y;
            Ks[cg + 2][row] = kv.z; Ks[cg + 3][row] = kv.w;
        }
        __syncthreads();
        #pragma unroll
        for (int kk = 0; kk < 16; kk++) {
            float a[8], b2[8];
            *(float4*)(a)      = *(const float4*)(&Qs[kk][ty * 8]);
            *(float4*)(a + 4)  = *(const float4*)(&Qs[kk][ty * 8 + 4]);
            *(float4*)(b2)     = *(const float4*)(&Ks[kk][tx * 8]);
            *(float4*)(b2 + 4) = *(const float4*)(&Ks[kk][tx * 8 + 4]);
            #pragma unroll
            for (int i = 0; i < 8; i++)
                #pragma unroll
                for (int j = 0; j < 8; j++)
                    acc[i][j] += a[i] * b2[j];
        }
        __syncthreads();
    }
    float* srow = S + ((long long)bh * LSEQ + i0) * LSEQ + j0;
    #pragma unroll
    for (int ii = 0; ii < 8; ii++) {
        const int gi = i0 + ty * 8 + ii;
        const int lo = gi - WWIN;
        float o[8];
        #pragma unroll
        for (int jj = 0; jj < 8; jj++) {
            int gj = j0 + tx * 8 + jj;
            bool masked = (gj >= lo) && (gj < gi);
            o[jj] = masked ? -1e10f : acc[ii][jj] * 0.125f;
        }
        float* cp = srow + (long long)(ty * 8 + ii) * LSEQ + tx * 8;
        *(float4*)(cp)     = make_float4(o[0], o[1], o[2], o[3]);
        *(float4*)(cp + 4) = make_float4(o[4], o[5], o[6], o[7]);
    }
}

// ---------------- softmax: warp per row, online max/sum over alive tiles, in-place ----
__global__ __launch_bounds__(256) void softmax_kernel(float* __restrict__ S) {
    const int warp = threadIdx.x >> 5, lane = threadIdx.x & 31;
    const long long row = (long long)blockIdx.x * 8 + warp;   // 0..B*H*L-1
    const int i = (int)(row & (LSEQ - 1));
    const int i0t = (i >> 7) << 7;                            // 128-tile base of this row
    float* srow = S + row * LSEQ;
    float m = -3.0e38f, l = 0.0f;
    for (int jt = 0; jt < 16; jt++) {
        const int j0 = jt << 7;
        if (tile_dead(i0t, j0)) continue;
        #pragma unroll
        for (int c = 0; c < 4; c++) {
            float s = srow[j0 + c * 32 + lane];
            float mn = fmaxf(m, s);
            l = l * __expf(m - mn) + __expf(s - mn);
            m = mn;
        }
    }
    #pragma unroll
    for (int off = 16; off; off >>= 1) {
        float m2 = __shfl_xor_sync(0xffffffffu, m, off);
        float l2 = __shfl_xor_sync(0xffffffffu, l, off);
        float mn = fmaxf(m, m2);
        l = l * __expf(m - mn) + l2 * __expf(m2 - mn);
        m = mn;
    }
    const float inv = 1.0f / l;
    for (int jt = 0; jt < 16; jt++) {
        const int j0 = jt << 7;
        if (tile_dead(i0t, j0)) continue;
        #pragma unroll
        for (int c = 0; c < 4; c++) {
            int idx = j0 + c * 32 + lane;
            srow[idx] = __expf(srow[idx] - m) * inv;
        }
    }
}

// ---------------- PV: O[b,i,h,:] = sum_j P[i,j] * V[b,j,kh,:]; skip dead tiles --------
__global__ __launch_bounds__(256) void pv_kernel(const float* __restrict__ P,
                                                 const float* __restrict__ V,
                                                 float* __restrict__ O) {
    const int bh = blockIdx.y;
    const int b = bh >> 5, h = bh & 31, kh = h >> 2;
    const int i0 = blockIdx.x * 128;
    __shared__ float Ps[32][128];
    __shared__ float Vs[32][64];
    const int tid = threadIdx.x, tx = tid & 15, ty = tid >> 4;
    const float* prow = P + ((long long)bh * LSEQ + i0) * LSEQ;
    const float* vbase = V + (long long)b * LSEQ * KVD + kh * HD;
    float acc[8][4] = {};
    for (int jt = 0; jt < 16; jt++) {
        const int j0 = jt << 7;
        if (tile_dead(i0, j0)) continue;
        for (int kc = 0; kc < 128; kc += 32) {
            #pragma unroll
            for (int t = 0; t < 4; t++) {
                int q = tid + t * 256;
                int r = q >> 3, c4 = (q & 7) * 4;
                float4 pv = *(const float4*)(prow + (long long)r * LSEQ + j0 + kc + c4);
                Ps[c4 + 0][r] = pv.x; Ps[c4 + 1][r] = pv.y;
                Ps[c4 + 2][r] = pv.z; Ps[c4 + 3][r] = pv.w;
            }
            #pragma unroll
            for (int t = 0; t < 2; t++) {
                int q = tid + t * 256;
                int kk = q >> 4, d4 = (q & 15) * 4;
                *(float4*)(&Vs[kk][d4]) =
                    *(const float4*)(vbase + (long long)(j0 + kc + kk) * KVD + d4);
            }
            __syncthreads();
            #pragma unroll
            for (int kk = 0; kk < 32; kk++) {
                float a[8], bb[4];
                *(float4*)(a)     = *(const float4*)(&Ps[kk][ty * 8]);
                *(float4*)(a + 4) = *(const float4*)(&Ps[kk][ty * 8 + 4]);
                *(float4*)(bb)    = *(const float4*)(&Vs[kk][tx * 4]);
                #pragma unroll
                for (int i = 0; i < 8; i++)
                    #pragma unroll
                    for (int j = 0; j < 4; j++)
                        acc[i][j] += a[i] * bb[j];
            }
            __syncthreads();
        }
    }
    #pragma unroll
    for (int ii = 0; ii < 8; ii++) {
        float* cp = O + (long long)(b * LSEQ + i0 + ty * 8 + ii) * DMODEL + h * HD + tx * 4;
        *(float4*)cp = make_float4(acc[ii][0], acc[ii][1], acc[ii][2], acc[ii][3]);
    }
}

// ---------------- launch -------------------------------------------------------------
extern "C" void kernel_launch(void* const* d_in, const int* in_sizes, int n_in,
                              void* d_out, int out_size) {
    const float* x  = (const float*)d_in[0];
    const float* wq = (const float*)d_in[1];
    const float* wk = (const float*)d_in[2];
    const float* wv = (const float*)d_in[3];
    const float* wo = (const float*)d_in[4];
    float* out = (float*)d_out;

    float *qb, *kb, *vb, *sb, *ab;
    cudaGetSymbolAddress((void**)&qb, g_q);
    cudaGetSymbolAddress((void**)&kb, g_k);
    cudaGetSymbolAddress((void**)&vb, g_v);
    cudaGetSymbolAddress((void**)&sb, g_s);
    cudaGetSymbolAddress((void**)&ab, g_ao);

    // Q projection: [4096,2048] = x @ wq
    sgemm128<<<dim3(DMODEL / 128, MROWS / 128), 256>>>(x, wq, qb, MROWS, DMODEL, DMODEL);
    // K and V projections fused: [4096,512] each
    sgemm128_kv<<<dim3(KVD / 128, MROWS / 128, 2), 256>>>(x, wk, wv, kb, vb);
    // Scores with mask (dead tiles skipped)
    scores_kernel<<<dim3(LSEQ / 128, LSEQ / 128, NB * NH), 256>>>(qb, kb, sb);
    // Softmax in place over alive tiles
    softmax_kernel<<<dim3((NB * NH * LSEQ) / 8), 256>>>(sb);
    // PV
    pv_kernel<<<dim3(LSEQ / 128, NB * NH), 256>>>(sb, vb, ab);
    // Output projection
    sgemm128<<<dim3(DMODEL / 128, MROWS / 128), 256>>>(ab, wo, out, MROWS, DMODEL, DMODEL);
}

// round 3
// speedup vs baseline: 1.9252x; 1.9252x over previous
#include <cuda_runtime.h>
#include <math.h>
#include <stdint.h>

// Problem constants
#define LSEQ 2048
#define DMODEL 2048
#define NH 32
#define NKV 8
#define HD 64
#define NB 2
#define WWIN 1024
#define KVD (NKV*HD)     // 512
#define MROWS (NB*LSEQ)  // 4096
#define PAD 36           // smem row stride (words): conflict-free fragment loads

// ---------------- scratch ----------------
static __device__ float g_q[(long long)MROWS * DMODEL];
static __device__ float g_k[(long long)MROWS * KVD];
static __device__ float g_v[(long long)MROWS * KVD];
static __device__ float g_s[(long long)NB * NH * LSEQ * LSEQ];
static __device__ float g_ao[(long long)MROWS * DMODEL];
static __device__ float g_wqt[(long long)DMODEL * DMODEL];
static __device__ float g_wkt[(long long)KVD * DMODEL];
static __device__ float g_wvt[(long long)KVD * DMODEL];
static __device__ float g_wot[(long long)DMODEL * DMODEL];
static __device__ float g_vt[(long long)NB * NKV * HD * LSEQ];

__host__ __device__ __forceinline__ bool tile_dead(int i0, int j0) {
    return (j0 + 127 < i0) && (j0 >= i0 + 127 - WWIN);
}

// ---------------- tf32 helpers ----------------
__device__ __forceinline__ uint32_t f2tf(float f) {
    uint32_t u;
    asm("cvt.rna.tf32.f32 %0, %1;" : "=r"(u) : "f"(f));
    return u;
}
__device__ __forceinline__ uint4 cvt4(float4 v) {
    uint4 u; u.x = f2tf(v.x); u.y = f2tf(v.y); u.z = f2tf(v.z); u.w = f2tf(v.w); return u;
}
// D += A@B^T fragment: m16n8k8, A row-major, B "col-major" (i.e. Bt[N,K] K-major)
__device__ __forceinline__ void mma8(float* c, const uint32_t* a, const uint32_t* b) {
    asm volatile("mma.sync.aligned.m16n8k8.row.col.f32.tf32.tf32.f32 "
        "{%0,%1,%2,%3}, {%4,%5,%6,%7}, {%8,%9}, {%0,%1,%2,%3};"
        : "+f"(c[0]), "+f"(c[1]), "+f"(c[2]), "+f"(c[3])
        : "r"(a[0]), "r"(a[1]), "r"(a[2]), "r"(a[3]), "r"(b[0]), "r"(b[1]));
}

// ---------------- generic tf32 GEMM: C[M,N] = A[M,K] @ Bt[N,K]^T ----------------
// CTA tile 128x128, 256 thr (8 warps, 2x4), warp tile 64x32, K-chunk 32, reg prefetch.
__global__ __launch_bounds__(256) void tc_gemm(const float* __restrict__ A,
                                               const float* __restrict__ Bt,
                                               float* __restrict__ C,
                                               int M, int N, int K) {
    __shared__ uint32_t As[128 * PAD];
    __shared__ uint32_t Bs[128 * PAD];
    const int t = threadIdx.x, w = t >> 5, lane = t & 31, g = lane >> 2, tg = lane & 3;
    const int wm = w >> 2, wn = w & 3;
    const long long m0 = (long long)blockIdx.y * 128, n0 = (long long)blockIdx.x * 128;
    const int lr = t >> 1, lc = (t & 1) * 16;
    const float* ap = A + (m0 + lr) * (long long)K + lc;
    const float* bp = Bt + (n0 + lr) * (long long)K + lc;

    float4 pa[4], pb[4];
    #pragma unroll
    for (int i = 0; i < 4; i++) { pa[i] = *(const float4*)(ap + i * 4); pb[i] = *(const float4*)(bp + i * 4); }

    float acc[4][4][4] = {};
    const int nch = K / 32;
    for (int c = 0; c < nch; c++) {
        #pragma unroll
        for (int i = 0; i < 4; i++) {
            *(uint4*)&As[lr * PAD + lc + i * 4] = cvt4(pa[i]);
            *(uint4*)&Bs[lr * PAD + lc + i * 4] = cvt4(pb[i]);
        }
        __syncthreads();
        if (c + 1 < nch) {
            #pragma unroll
            for (int i = 0; i < 4; i++) {
                pa[i] = *(const float4*)(ap + (c + 1) * 32 + i * 4);
                pb[i] = *(const float4*)(bp + (c + 1) * 32 + i * 4);
            }
        }
        #pragma unroll
        for (int kk = 0; kk < 4; kk++) {
            const int k0 = kk * 8;
            uint32_t af[4][4], bf[4][2];
            #pragma unroll
            for (int fm = 0; fm < 4; fm++) {
                const int r = wm * 64 + fm * 16 + g;
                af[fm][0] = As[r * PAD + k0 + tg];       af[fm][1] = As[(r + 8) * PAD + k0 + tg];
                af[fm][2] = As[r * PAD + k0 + tg + 4];   af[fm][3] = As[(r + 8) * PAD + k0 + tg + 4];
            }
            #pragma unroll
            for (int fn = 0; fn < 4; fn++) {
                const int n = wn * 32 + fn * 8 + g;
                bf[fn][0] = Bs[n * PAD + k0 + tg];       bf[fn][1] = Bs[n * PAD + k0 + tg + 4];
            }
            #pragma unroll
            for (int fm = 0; fm < 4; fm++)
                #pragma unroll
                for (int fn = 0; fn < 4; fn++)
                    mma8(acc[fm][fn], af[fm], bf[fn]);
        }
        __syncthreads();
    }
    #pragma unroll
    for (int fm = 0; fm < 4; fm++) {
        const long long r0 = m0 + wm * 64 + fm * 16 + g;
        #pragma unroll
        for (int fn = 0; fn < 4; fn++) {
            const long long cc = n0 + wn * 32 + fn * 8 + 2 * tg;
            *(float2*)(C + r0 * N + cc)       = make_float2(acc[fm][fn][0], acc[fm][fn][1]);
            *(float2*)(C + (r0 + 8) * N + cc) = make_float2(acc[fm][fn][2], acc[fm][fn][3]);
        }
    }
}

// ---------------- scores: S = mask(QK^T / 8), skip dead tiles ----------------
__global__ __launch_bounds__(256) void tc_scores(const float* __restrict__ Q,
                                                 const float* __restrict__ Kb,
                                                 float* __restrict__ S) {
    const int bh = blockIdx.z, b = bh >> 5, h = bh & 31, kh = h >> 2;
    const int i0 = blockIdx.y * 128, j0 = blockIdx.x * 128;
    if (tile_dead(i0, j0)) return;
    __shared__ uint32_t As[128 * PAD];
    __shared__ uint32_t Bs[128 * PAD];
    const int t = threadIdx.x, w = t >> 5, lane = t & 31, g = lane >> 2, tg = lane & 3;
    const int wm = w >> 2, wn = w & 3;
    const int lr = t >> 1, lc = (t & 1) * 16;
    const float* qp = Q + ((long long)(b * LSEQ + i0 + lr)) * DMODEL + h * HD + lc;
    const float* kp = Kb + ((long long)(b * LSEQ + j0 + lr)) * KVD + kh * HD + lc;

    float acc[4][4][4] = {};
    for (int c = 0; c < 2; c++) {
        #pragma unroll
        for (int i = 0; i < 4; i++) {
            *(uint4*)&As[lr * PAD + lc + i * 4] = cvt4(*(const float4*)(qp + c * 32 + i * 4));
            *(uint4*)&Bs[lr * PAD + lc + i * 4] = cvt4(*(const float4*)(kp + c * 32 + i * 4));
        }
        __syncthreads();
        #pragma unroll
        for (int kk = 0; kk < 4; kk++) {
            const int k0 = kk * 8;
            uint32_t af[4][4], bf[4][2];
            #pragma unroll
            for (int fm = 0; fm < 4; fm++) {
                const int r = wm * 64 + fm * 16 + g;
                af[fm][0] = As[r * PAD + k0 + tg];       af[fm][1] = As[(r + 8) * PAD + k0 + tg];
                af[fm][2] = As[r * PAD + k0 + tg + 4];   af[fm][3] = As[(r + 8) * PAD + k0 + tg + 4];
            }
            #pragma unroll
            for (int fn = 0; fn < 4; fn++) {
                const int n = wn * 32 + fn * 8 + g;
                bf[fn][0] = Bs[n * PAD + k0 + tg];       bf[fn][1] = Bs[n * PAD + k0 + tg + 4];
            }
            #pragma unroll
            for (int fm = 0; fm < 4; fm++)
                #pragma unroll
                for (int fn = 0; fn < 4; fn++)
                    mma8(acc[fm][fn], af[fm], bf[fn]);
        }
        __syncthreads();
    }
    #pragma unroll
    for (int fm = 0; fm < 4; fm++) {
        #pragma unroll
        for (int rr = 0; rr < 2; rr++) {
            const int gi = i0 + wm * 64 + fm * 16 + g + rr * 8;
            float* srow = S + ((long long)bh * LSEQ + gi) * LSEQ;
            #pragma unroll
            for (int fn = 0; fn < 4; fn++) {
                const int gj = j0 + wn * 32 + fn * 8 + 2 * tg;
                const float v0 = acc[fm][fn][rr * 2], v1 = acc[fm][fn][rr * 2 + 1];
                const bool m0b = (gj >= gi - WWIN) && (gj < gi);
                const bool m1b = (gj + 1 >= gi - WWIN) && (gj + 1 < gi);
                *(float2*)(srow + gj) = make_float2(m0b ? -1e10f : v0 * 0.125f,
                                                    m1b ? -1e10f : v1 * 0.125f);
            }
        }
    }
}

// ---------------- softmax (memory-bound; unchanged) ----------------
__global__ __launch_bounds__(256) void softmax_kernel(float* __restrict__ S) {
    const int warp = threadIdx.x >> 5, lane = threadIdx.x & 31;
    const long long row = (long long)blockIdx.x * 8 + warp;
    const int i = (int)(row & (LSEQ - 1));
    const int i0t = (i >> 7) << 7;
    float* srow = S + row * LSEQ;
    float m = -3.0e38f, l = 0.0f;
    for (int jt = 0; jt < 16; jt++) {
        const int j0 = jt << 7;
        if (tile_dead(i0t, j0)) continue;
        #pragma unroll
        for (int c = 0; c < 4; c++) {
            float s = srow[j0 + c * 32 + lane];
            float mn = fmaxf(m, s);
            l = l * __expf(m - mn) + __expf(s - mn);
            m = mn;
        }
    }
    #pragma unroll
    for (int off = 16; off; off >>= 1) {
        float m2 = __shfl_xor_sync(0xffffffffu, m, off);
        float l2 = __shfl_xor_sync(0xffffffffu, l, off);
        float mn = fmaxf(m, m2);
        l = l * __expf(m - mn) + l2 * __expf(m2 - mn);
        m = mn;
    }
    const float inv = 1.0f / l;
    for (int jt = 0; jt < 16; jt++) {
        const int j0 = jt << 7;
        if (tile_dead(i0t, j0)) continue;
        #pragma unroll
        for (int c = 0; c < 4; c++) {
            int idx = j0 + c * 32 + lane;
            srow[idx] = __expf(srow[idx] - m) * inv;
        }
    }
}

// ---------------- PV: O = P @ V (Vt is [b,kh][HD][L] K-major); skip dead tiles -------
__global__ __launch_bounds__(256) void tc_pv(const float* __restrict__ P,
                                             const float* __restrict__ Vt,
                                             float* __restrict__ O) {
    const int bh = blockIdx.y, b = bh >> 5, h = bh & 31, kh = h >> 2;
    const int i0 = blockIdx.x * 128;
    __shared__ uint32_t As[128 * PAD];
    __shared__ uint32_t Bs[64 * PAD];
    const int t = threadIdx.x, w = t >> 5, lane = t & 31, g = lane >> 2, tg = lane & 3;
    const int wm = w >> 1, wn = w & 1;   // 4x2 warp grid: warp tile 32x32
    const int lr = t >> 1, lc = (t & 1) * 16;      // A loads: 128 rows x 32 cols
    const int vr = t >> 2, vc = (t & 3) * 8;       // B loads: 64 rows x 32 cols

    int aj[16], na = 0;
    for (int jt = 0; jt < 16; jt++) {
        const int j0 = jt << 7;
        if (!tile_dead(i0, j0)) aj[na++] = j0;
    }
    const int nch = na * 4;

    const float* prow = P + ((long long)bh * LSEQ + i0 + lr) * LSEQ;
    const float* vrow = Vt + ((long long)((b * NKV + kh) * HD) + vr) * LSEQ;

    float4 pa[4], pb[2];
    {
        const int jc = aj[0] + lc;
        #pragma unroll
        for (int i = 0; i < 4; i++) pa[i] = *(const float4*)(prow + jc + i * 4);
        const int jv = aj[0] + vc;
        pb[0] = *(const float4*)(vrow + jv);
        pb[1] = *(const float4*)(vrow + jv + 4);
    }

    float acc[2][4][4] = {};
    for (int ci = 0; ci < nch; ci++) {
        #pragma unroll
        for (int i = 0; i < 4; i++)
            *(uint4*)&As[lr * PAD + lc + i * 4] = cvt4(pa[i]);
        *(uint4*)&Bs[vr * PAD + vc]     = cvt4(pb[0]);
        *(uint4*)&Bs[vr * PAD + vc + 4] = cvt4(pb[1]);
        __syncthreads();
        if (ci + 1 < nch) {
            const int j2 = aj[(ci + 1) >> 2] + ((ci + 1) & 3) * 32;
            #pragma unroll
            for (int i = 0; i < 4; i++) pa[i] = *(const float4*)(prow + j2 + lc + i * 4);
            pb[0] = *(const float4*)(vrow + j2 + vc);
            pb[1] = *(const float4*)(vrow + j2 + vc + 4);
        }
        #pragma unroll
        for (int kk = 0; kk < 4; kk++) {
            const int k0 = kk * 8;
            uint32_t af[2][4], bf[4][2];
            #pragma unroll
            for (int fm = 0; fm < 2; fm++) {
                const int r = wm * 32 + fm * 16 + g;
                af[fm][0] = As[r * PAD + k0 + tg];       af[fm][1] = As[(r + 8) * PAD + k0 + tg];
                af[fm][2] = As[r * PAD + k0 + tg + 4];   af[fm][3] = As[(r + 8) * PAD + k0 + tg + 4];
            }
            #pragma unroll
            for (int fn = 0; fn < 4; fn++) {
                const int n = wn * 32 + fn * 8 + g;
                bf[fn][0] = Bs[n * PAD + k0 + tg];       bf[fn][1] = Bs[n * PAD + k0 + tg + 4];
            }
            #pragma unroll
            for (int fm = 0; fm < 2; fm++)
                #pragma unroll
                for (int fn = 0; fn < 4; fn++)
                    mma8(acc[fm][fn], af[fm], bf[fn]);
        }
        __syncthreads();
    }
    #pragma unroll
    for (int fm = 0; fm < 2; fm++) {
        const long long r0 = i0 + wm * 32 + fm * 16 + g;
        #pragma unroll
        for (int fn = 0; fn < 4; fn++) {
            const int cc = h * HD + wn * 32 + fn * 8 + 2 * tg;
            float* cp0 = O + ((long long)(b * LSEQ) + r0) * DMODEL + cc;
            *(float2*)(cp0)              = make_float2(acc[fm][fn][0], acc[fm][fn][1]);
            *(float2*)(cp0 + 8LL * DMODEL) = make_float2(acc[fm][fn][2], acc[fm][fn][3]);
        }
    }
}

// ---------------- transposes ----------------
__global__ void transpose_k(const float* __restrict__ src, float* __restrict__ dst, int R, int C) {
    __shared__ float tb[32][33];
    const int c = blockIdx.x * 32, r = blockIdx.y * 32;
    const int tx = threadIdx.x, ty = threadIdx.y;
    #pragma unroll
    for (int i = 0; i < 32; i += 8) tb[ty + i][tx] = src[(long long)(r + ty + i) * C + c + tx];
    __syncthreads();
    #pragma unroll
    for (int i = 0; i < 32; i += 8) dst[(long long)(c + ty + i) * R + r + tx] = tb[tx][ty + i];
}
__global__ void vtrans_k(const float* __restrict__ V, float* __restrict__ Vt) {
    __shared__ float tb[32][33];
    const int bkh = blockIdx.z, b = bkh >> 3, kh = bkh & 7;
    const int j0 = blockIdx.x * 32, d0 = blockIdx.y * 32;
    const int tx = threadIdx.x, ty = threadIdx.y;
    #pragma unroll
    for (int i = 0; i < 32; i += 8)
        tb[ty + i][tx] = V[(long long)(b * LSEQ + j0 + ty + i) * KVD + kh * HD + d0 + tx];
    __syncthreads();
    #pragma unroll
    for (int i = 0; i < 32; i += 8)
        Vt[((long long)bkh * HD + d0 + ty + i) * LSEQ + j0 + tx] = tb[tx][ty + i];
}

// ---------------- launch ----------------
extern "C" void kernel_launch(void* const* d_in, const int* in_sizes, int n_in,
                              void* d_out, int out_size) {
    const float* x  = (const float*)d_in[0];
    const float* wq = (const float*)d_in[1];
    const float* wk = (const float*)d_in[2];
    const float* wv = (const float*)d_in[3];
    const float* wo = (const float*)d_in[4];
    float* out = (float*)d_out;

    float *qb, *kb, *vb, *sb, *ab, *wqt, *wkt, *wvt, *wot, *vt;
    cudaGetSymbolAddress((void**)&qb, g_q);
    cudaGetSymbolAddress((void**)&kb, g_k);
    cudaGetSymbolAddress((void**)&vb, g_v);
    cudaGetSymbolAddress((void**)&sb, g_s);
    cudaGetSymbolAddress((void**)&ab, g_ao);
    cudaGetSymbolAddress((void**)&wqt, g_wqt);
    cudaGetSymbolAddress((void**)&wkt, g_wkt);
    cudaGetSymbolAddress((void**)&wvt, g_wvt);
    cudaGetSymbolAddress((void**)&wot, g_wot);
    cudaGetSymbolAddress((void**)&vt, g_vt);

    dim3 tb32(32, 8);
    // weight transposes to K-major (N-major rows)
    transpose_k<<<dim3(64, 64), tb32>>>(wq, wqt, DMODEL, DMODEL);
    transpose_k<<<dim3(16, 64), tb32>>>(wk, wkt, DMODEL, KVD);
    transpose_k<<<dim3(16, 64), tb32>>>(wv, wvt, DMODEL, KVD);
    transpose_k<<<dim3(64, 64), tb32>>>(wo, wot, DMODEL, DMODEL);
    // projections (tf32 mma.sync)
    tc_gemm<<<dim3(16, 32), 256>>>(x, wqt, qb, MROWS, DMODEL, DMODEL);
    tc_gemm<<<dim3(4, 32), 256>>>(x, wkt, kb, MROWS, KVD, DMODEL);
    tc_gemm<<<dim3(4, 32), 256>>>(x, wvt, vb, MROWS, KVD, DMODEL);
    // V transpose for PV B-operand
    vtrans_k<<<dim3(64, 2, 16), tb32>>>(vb, vt);
    // attention
    tc_scores<<<dim3(16, 16, NB * NH), 256>>>(qb, kb, sb);
    softmax_kernel<<<dim3((NB * NH * LSEQ) / 8), 256>>>(sb);
    tc_pv<<<dim3(16, NB * NH), 256>>>(sb, vt, ab);
    // output projection
    tc_gemm<<<dim3(16, 32), 256>>>(ab, wot, out, MROWS, DMODEL, DMODEL);
}